// round 16
// baseline (speedup 1.0000x reference)
#include <cuda_runtime.h>
#include <cuda_bf16.h>
#include <math.h>
#include <stdint.h>

#define BB 2
#define TT 2048
#define CC 1024
#define HH 16
#define DD 64
#define MM (BB*TT)      // 4096
#define QT2 16          // 128-row query tiles

// Scratch (device globals: allocation-free, graph-capture safe)
__device__ float g_V[BB*HH*TT*DD];
__device__ float g_Y[BB*HH*TT*DD];
__device__ float g_Yn[MM*CC];                            // GroupNorm-applied Y (f32)
__device__ __nv_bfloat16 g_Qh[BB*HH*TT*DD], g_Ql[BB*HH*TT*DD];
__device__ __nv_bfloat16 g_Kh[BB*HH*TT*DD], g_Kl[BB*HH*TT*DD];
__device__ __nv_bfloat16 g_Vth[BB*HH*DD*TT], g_Vtl[BB*HH*DD*TT];  // [bh][d][t]
__device__ float g_part[BB*HH*QT2*2];
__device__ float g_norm[BB*HH*2];

// ===========================================================================
// MMA wrappers (baseline ISA — sm_103-safe)
// ===========================================================================
__device__ __forceinline__ void mma16816(float d[4], const uint32_t a[4],
                                         const uint32_t b[2]) {
    asm volatile(
        "mma.sync.aligned.m16n8k16.row.col.f32.bf16.bf16.f32 "
        "{%0,%1,%2,%3}, {%4,%5,%6,%7}, {%8,%9}, {%0,%1,%2,%3};"
        : "+f"(d[0]), "+f"(d[1]), "+f"(d[2]), "+f"(d[3])
        : "r"(a[0]), "r"(a[1]), "r"(a[2]), "r"(a[3]), "r"(b[0]), "r"(b[1]));
}

// tf32 m16n8k8: A frag {(g,tg),(g+8,tg),(g,tg+4),(g+8,tg+4)}, B {(tg,g),(tg+4,g)}
__device__ __forceinline__ void mma1688t(float d[4], const uint32_t a[4],
                                         uint32_t b0, uint32_t b1) {
    asm volatile(
        "mma.sync.aligned.m16n8k8.row.col.f32.tf32.tf32.f32 "
        "{%0,%1,%2,%3}, {%4,%5,%6,%7}, {%8,%9}, {%0,%1,%2,%3};"
        : "+f"(d[0]), "+f"(d[1]), "+f"(d[2]), "+f"(d[3])
        : "r"(a[0]), "r"(a[1]), "r"(a[2]), "r"(a[3]), "r"(b0), "r"(b1));
}

__device__ __forceinline__ uint32_t f2tf32(float x) {
    uint32_t r;
    asm("cvt.rna.tf32.f32 %0, %1;" : "=r"(r) : "f"(x));
    return r;
}

__device__ __forceinline__ void cvt_pair(float a, float b, uint32_t& hi, uint32_t& lo) {
    __nv_bfloat162 h, l;
    h.x = __float2bfloat16(a); h.y = __float2bfloat16(b);
    l.x = __float2bfloat16(a - __bfloat162float(h.x));
    l.y = __float2bfloat16(b - __bfloat162float(h.y));
    hi = *(uint32_t*)&h; lo = *(uint32_t*)&l;
}

// ===========================================================================
// tf32 GEMM: D[m,n] = sum_k A[m,k] * W[n,k], f32 operands read directly,
// cvt.rna -> tf32 in the loader. CTA 128x128, Kch 64, 256 thr, warps 4x2,
// warp tile 32x64, k8 steps. SMEM pad 68 f32 -> conflict-free ((4g+tg)%32).
// mode 0: Q -> g_Qh/g_Ql (scaled, split for bf16 retention);
// mode 1: K -> g_Kh/g_Kl;  mode 2: V -> g_V f32;  mode 3: -> OutDirect.
// ===========================================================================
#define KCH 64
#define FSTR 68
#define FTILE (128*FSTR)
#define GEMM_SMEM (2*FTILE*4)            // 69632 B (2 CTAs/SM fits)

__global__ void __launch_bounds__(256, 2)
gemm_kernel(const float* __restrict__ A, const float* __restrict__ W,
            float* __restrict__ OutDirect, int mode, float scale) {
    extern __shared__ uint32_t smU[];
    uint32_t* As = smU;
    uint32_t* Bs = smU + FTILE;

    int tid = threadIdx.x;
    int wid = tid >> 5, lane = tid & 31;
    int g = lane >> 2, tg = lane & 3;
    int wm = wid >> 1, wn = wid & 1;
    int m0 = blockIdx.x * 128, n0 = blockIdx.y * 128;

    const float* Ap = A ? A : g_Yn;
    int lrow = tid >> 1, lhalf = (tid & 1) * 32;
    const float* Arow = Ap + (size_t)(m0 + lrow) * CC + lhalf;
    const float* Brow = W  + (size_t)(n0 + lrow) * CC + lhalf;

    float acc[2][8][4] = {};

    for (int k0 = 0; k0 < CC; k0 += KCH) {
        int u = lrow*FSTR + lhalf;
        #pragma unroll
        for (int j = 0; j < 8; j++) {
            float4 a = *(const float4*)(Arow + k0 + j*4);
            uint4 ta = make_uint4(f2tf32(a.x), f2tf32(a.y), f2tf32(a.z), f2tf32(a.w));
            *(uint4*)(As + u + j*4) = ta;
            float4 b = *(const float4*)(Brow + k0 + j*4);
            uint4 tb = make_uint4(f2tf32(b.x), f2tf32(b.y), f2tf32(b.z), f2tf32(b.w));
            *(uint4*)(Bs + u + j*4) = tb;
        }
        __syncthreads();

        #pragma unroll
        for (int ks = 0; ks < 8; ks++) {
            int kc = ks*8 + tg;
            uint32_t a[2][4];
            #pragma unroll
            for (int mf = 0; mf < 2; mf++) {
                int r = wm*32 + mf*16 + g;
                a[mf][0] = As[(r  )*FSTR + kc];
                a[mf][1] = As[(r+8)*FSTR + kc];
                a[mf][2] = As[(r  )*FSTR + kc + 4];
                a[mf][3] = As[(r+8)*FSTR + kc + 4];
            }
            #pragma unroll
            for (int nf = 0; nf < 8; nf++) {
                int n = wn*64 + nf*8 + g;
                uint32_t b0 = Bs[n*FSTR + kc];
                uint32_t b1 = Bs[n*FSTR + kc + 4];
                mma1688t(acc[0][nf], a[0], b0, b1);
                mma1688t(acc[1][nf], a[1], b0, b1);
            }
        }
        __syncthreads();
    }

    if (mode == 3) {
        #pragma unroll
        for (int mf = 0; mf < 2; mf++) {
            int m = m0 + wm*32 + mf*16 + g;
            #pragma unroll
            for (int nf = 0; nf < 8; nf++) {
                int n = n0 + wn*64 + nf*8 + tg*2;
                float* d = acc[mf][nf];
                *(float2*)(OutDirect + (size_t)m*CC + n)     = make_float2(d[0], d[1]);
                *(float2*)(OutDirect + (size_t)(m+8)*CC + n) = make_float2(d[2], d[3]);
            }
        }
    } else if (mode == 2) {
        #pragma unroll
        for (int mf = 0; mf < 2; mf++) {
            int m = m0 + wm*32 + mf*16 + g;
            int b = m >> 11, t = m & (TT - 1);
            #pragma unroll
            for (int nf = 0; nf < 8; nf++) {
                int n = n0 + wn*64 + nf*8 + tg*2;
                int h = n >> 6, d0 = n & 63;
                float* d = acc[mf][nf];
                size_t base = ((size_t)(b*HH + h)*TT);
                *(float2*)(g_V + (base + t  )*DD + d0) = make_float2(d[0], d[1]);
                *(float2*)(g_V + (base + t+8)*DD + d0) = make_float2(d[2], d[3]);
            }
        }
    } else {
        __nv_bfloat16* Oh = (mode == 0) ? g_Qh : g_Kh;
        __nv_bfloat16* Ol = (mode == 0) ? g_Ql : g_Kl;
        #pragma unroll
        for (int mf = 0; mf < 2; mf++) {
            int m = m0 + wm*32 + mf*16 + g;
            int b = m >> 11, t = m & (TT - 1);
            #pragma unroll
            for (int nf = 0; nf < 8; nf++) {
                int n = n0 + wn*64 + nf*8 + tg*2;
                int h = n >> 6, d0 = n & 63;
                float* d = acc[mf][nf];
                size_t base = ((size_t)(b*HH + h)*TT);
                uint32_t h0, l0, h1, l1;
                cvt_pair(d[0]*scale, d[1]*scale, h0, l0);
                cvt_pair(d[2]*scale, d[3]*scale, h1, l1);
                *(uint32_t*)(Oh + (base + t  )*DD + d0) = h0;
                *(uint32_t*)(Ol + (base + t  )*DD + d0) = l0;
                *(uint32_t*)(Oh + (base + t+8)*DD + d0) = h1;
                *(uint32_t*)(Ol + (base + t+8)*DD + d0) = l1;
            }
        }
    }
}

// ===========================================================================
// V transpose + split: g_V [bh][t][d] f32 -> g_Vth/g_Vtl [bh][d][t] bf16
// ===========================================================================
__global__ void vt_kernel() {
    __shared__ float ts[64][65];
    int bh = blockIdx.y, t0 = blockIdx.x * 64;
    size_t base = (size_t)bh * TT * DD;
    int tid = threadIdx.x;
    int r = tid >> 2, c = (tid & 3) * 16;

    #pragma unroll
    for (int i = 0; i < 4; i++) {
        float4 v = *(const float4*)(g_V + base + (size_t)(t0 + r)*DD + c + i*4);
        ts[r][c + i*4 + 0] = v.x; ts[r][c + i*4 + 1] = v.y;
        ts[r][c + i*4 + 2] = v.z; ts[r][c + i*4 + 3] = v.w;
    }
    __syncthreads();

    uint32_t hh[8], ll[8];
    #pragma unroll
    for (int p = 0; p < 8; p++)
        cvt_pair(ts[c + 2*p][r], ts[c + 2*p + 1][r], hh[p], ll[p]);
    size_t o = base + (size_t)r*TT + t0 + c;
    *(uint4*)(g_Vth + o)     = make_uint4(hh[0], hh[1], hh[2], hh[3]);
    *(uint4*)(g_Vth + o + 8) = make_uint4(hh[4], hh[5], hh[6], hh[7]);
    *(uint4*)(g_Vtl + o)     = make_uint4(ll[0], ll[1], ll[2], ll[3]);
    *(uint4*)(g_Vtl + o + 8) = make_uint4(ll[4], ll[5], ll[6], ll[7]);
}

// ===========================================================================
// Retention, bf16 split tensor-core version (unchanged from R15 passing).
// ===========================================================================
#define RSTR 72
#define RET_SMEM ((128*RSTR*2 + 64*RSTR*4) * 2)   // 73728 B

__global__ void __launch_bounds__(256, 2) retention_kernel() {
    extern __shared__ __nv_bfloat16 sb[];
    __nv_bfloat16* SQh = sb;
    __nv_bfloat16* SQl = sb + 128*RSTR;
    __nv_bfloat16* SKh = sb + 256*RSTR;
    __nv_bfloat16* SKl = sb + 320*RSTR;
    __nv_bfloat16* SVh = sb + 384*RSTR;
    __nv_bfloat16* SVl = sb + 448*RSTR;
    __shared__ float red[16];

    int tid = threadIdx.x;
    int w = tid >> 5, lane = tid & 31, g = lane >> 2, tg = lane & 3;
    int qt = (QT2 - 1) - blockIdx.x;           // heavy tiles first
    int bh = blockIdx.y;
    int h = bh & (HH - 1);
    int i0 = qt * 128;
    size_t base = (size_t)bh * TT * DD;

    float lg = log2f(1.0f - exp2f(-5.0f - 0.5f * (float)h));

    // load Q tile (128 x 64) hi/lo
    {
        int r = tid >> 1, sq = (tid & 1) * 32;
        const __nv_bfloat16* qh = g_Qh + base + (size_t)(i0 + r)*DD + sq;
        const __nv_bfloat16* ql = g_Ql + base + (size_t)(i0 + r)*DD + sq;
        #pragma unroll
        for (int cch = 0; cch < 4; cch++) {
            *(uint4*)(SQh + r*RSTR + sq + cch*8) = *(const uint4*)(qh + cch*8);
            *(uint4*)(SQl + r*RSTR + sq + cch*8) = *(const uint4*)(ql + cch*8);
        }
    }

    // constant decay factors (reg-lean)
    float rowA = exp2f(lg * (float)(w*16 + g));
    float rowB = rowA * exp2f(lg * 8.0f);
    float cstep = exp2f(-lg);
    float cf0[8];
    #pragma unroll
    for (int nf = 0; nf < 8; nf++)
        cf0[nf] = exp2f(-lg * (float)(nf*8 + tg*2));

    float acc_o[8][4] = {};
    int r4 = tid >> 2, s4 = (tid & 3) * 16;
    int jend = i0 + 128;

    for (int j0 = 0; j0 < jend; j0 += 64) {
        __syncthreads();
        {
            const __nv_bfloat16* kh = g_Kh + base + (size_t)(j0 + r4)*DD + s4;
            const __nv_bfloat16* kl = g_Kl + base + (size_t)(j0 + r4)*DD + s4;
            const __nv_bfloat16* vh = g_Vth + base + (size_t)r4*TT + j0 + s4;
            const __nv_bfloat16* vl = g_Vtl + base + (size_t)r4*TT + j0 + s4;
            *(uint4*)(SKh + r4*RSTR + s4)     = *(const uint4*)(kh);
            *(uint4*)(SKh + r4*RSTR + s4 + 8) = *(const uint4*)(kh + 8);
            *(uint4*)(SKl + r4*RSTR + s4)     = *(const uint4*)(kl);
            *(uint4*)(SKl + r4*RSTR + s4 + 8) = *(const uint4*)(kl + 8);
            *(uint4*)(SVh + r4*RSTR + s4)     = *(const uint4*)(vh);
            *(uint4*)(SVh + r4*RSTR + s4 + 8) = *(const uint4*)(vh + 8);
            *(uint4*)(SVl + r4*RSTR + s4)     = *(const uint4*)(vl);
            *(uint4*)(SVl + r4*RSTR + s4 + 8) = *(const uint4*)(vl + 8);
        }
        __syncthreads();

        int iMin = i0 + w*16, iMax = iMin + 15, jMax = j0 + 63;
        if (iMax < j0) continue;

        // ---- S = Q K^T ----
        float s[8][4] = {};
        #pragma unroll
        for (int ks = 0; ks < 4; ks++) {
            int kc = ks*16 + tg*2;
            int ra = (w*16 + g)*RSTR, rb = ra + 8*RSTR;
            uint32_t ah[4], al[4];
            ah[0] = *(const uint32_t*)(SQh + ra + kc);
            ah[1] = *(const uint32_t*)(SQh + rb + kc);
            ah[2] = *(const uint32_t*)(SQh + ra + kc + 8);
            ah[3] = *(const uint32_t*)(SQh + rb + kc + 8);
            al[0] = *(const uint32_t*)(SQl + ra + kc);
            al[1] = *(const uint32_t*)(SQl + rb + kc);
            al[2] = *(const uint32_t*)(SQl + ra + kc + 8);
            al[3] = *(const uint32_t*)(SQl + rb + kc + 8);
            #pragma unroll
            for (int nf = 0; nf < 8; nf++) {
                int n = (nf*8 + g)*RSTR;
                uint32_t bh2[2], bl2[2];
                bh2[0] = *(const uint32_t*)(SKh + n + kc);
                bh2[1] = *(const uint32_t*)(SKh + n + kc + 8);
                bl2[0] = *(const uint32_t*)(SKl + n + kc);
                bl2[1] = *(const uint32_t*)(SKl + n + kc + 8);
                mma16816(s[nf], ah, bh2);
                mma16816(s[nf], ah, bl2);
                mma16816(s[nf], al, bh2);
            }
        }

        // ---- decay / causal mask ----
        if (iMin >= jMax) {
            float tf = exp2f(lg * (float)(i0 - j0));
            float fA = rowA * tf, fB = rowB * tf;
            #pragma unroll
            for (int nf = 0; nf < 8; nf++) {
                float c0 = cf0[nf], c1 = c0 * cstep;
                s[nf][0] *= fA * c0;
                s[nf][1] *= fA * c1;
                s[nf][2] *= fB * c0;
                s[nf][3] *= fB * c1;
            }
        } else {
            int riA = iMin + g, riB = riA + 8;
            #pragma unroll
            for (int nf = 0; nf < 8; nf++) {
                int jg = j0 + nf*8 + tg*2;
                int d0 = riA - jg, d1 = d0 - 1, d2 = riB - jg, d3 = d2 - 1;
                s[nf][0] = (d0 >= 0) ? s[nf][0] * exp2f(lg * (float)d0) : 0.0f;
                s[nf][1] = (d1 >= 0) ? s[nf][1] * exp2f(lg * (float)d1) : 0.0f;
                s[nf][2] = (d2 >= 0) ? s[nf][2] * exp2f(lg * (float)d2) : 0.0f;
                s[nf][3] = (d3 >= 0) ? s[nf][3] * exp2f(lg * (float)d3) : 0.0f;
            }
        }

        // ---- O += S V ----
        #pragma unroll
        for (int ks = 0; ks < 4; ks++) {
            uint32_t sh[4], sl[4];
            cvt_pair(s[2*ks  ][0], s[2*ks  ][1], sh[0], sl[0]);
            cvt_pair(s[2*ks  ][2], s[2*ks  ][3], sh[1], sl[1]);
            cvt_pair(s[2*ks+1][0], s[2*ks+1][1], sh[2], sl[2]);
            cvt_pair(s[2*ks+1][2], s[2*ks+1][3], sh[3], sl[3]);
            int kc = ks*16 + tg*2;
            #pragma unroll
            for (int nd = 0; nd < 8; nd++) {
                int n = (nd*8 + g)*RSTR;
                uint32_t vh[2], vl[2];
                vh[0] = *(const uint32_t*)(SVh + n + kc);
                vh[1] = *(const uint32_t*)(SVh + n + kc + 8);
                vl[0] = *(const uint32_t*)(SVl + n + kc);
                vl[1] = *(const uint32_t*)(SVl + n + kc + 8);
                mma16816(acc_o[nd], sh, vh);
                mma16816(acc_o[nd], sh, vl);
                mma16816(acc_o[nd], sl, vh);
            }
        }
    }

    // ---- write y + GroupNorm partial stats ----
    float lsum = 0.0f, lsq = 0.0f;
    int riA = i0 + w*16 + g;
    #pragma unroll
    for (int nd = 0; nd < 8; nd++) {
        int d0 = nd*8 + tg*2;
        float* d = acc_o[nd];
        lsum += d[0] + d[1] + d[2] + d[3];
        lsq  += d[0]*d[0] + d[1]*d[1] + d[2]*d[2] + d[3]*d[3];
        *(float2*)(g_Y + base + (size_t)riA*DD + d0)     = make_float2(d[0], d[1]);
        *(float2*)(g_Y + base + (size_t)(riA+8)*DD + d0) = make_float2(d[2], d[3]);
    }
    #pragma unroll
    for (int o = 16; o > 0; o >>= 1) {
        lsum += __shfl_down_sync(0xffffffffu, lsum, o);
        lsq  += __shfl_down_sync(0xffffffffu, lsq,  o);
    }
    if (lane == 0) { red[w*2] = lsum; red[w*2 + 1] = lsq; }
    __syncthreads();
    if (tid == 0) {
        float s0 = 0.0f, s1 = 0.0f;
        #pragma unroll
        for (int x = 0; x < 8; x++) { s0 += red[x*2]; s1 += red[x*2 + 1]; }
        g_part[(bh*QT2 + qt)*2 + 0] = s0;
        g_part[(bh*QT2 + qt)*2 + 1] = s1;
    }
}

__global__ void norm_stats_kernel() {
    int i = threadIdx.x;
    if (i < BB*HH) {
        float s = 0.0f, q = 0.0f;
        for (int t = 0; t < QT2; t++) {
            s += g_part[(i*QT2 + t)*2 + 0];
            q += g_part[(i*QT2 + t)*2 + 1];
        }
        float n = (float)(TT * DD);
        float mu = s / n;
        float var = q / n - mu * mu;
        g_norm[i*2 + 0] = mu;
        g_norm[i*2 + 1] = rsqrtf(var + 1e-5f);
    }
}

// GroupNorm apply -> g_Yn f32 (A operand for the tf32 output GEMM)
__global__ void yn_kernel(const float* __restrict__ gnw, const float* __restrict__ gnb) {
    int m = blockIdx.x;
    int k = threadIdx.x * 4;
    int b = m >> 11, t = m & (TT - 1);
    int h = k >> 6, d = k & 63;
    int bh = b*HH + h;
    float mu = g_norm[bh*2 + 0], ri = g_norm[bh*2 + 1];
    float4 y = *(const float4*)(g_Y + ((size_t)bh*TT + t)*DD + d);
    float4 w = *(const float4*)(gnw + k);
    float4 gb = *(const float4*)(gnb + k);
    float4 o;
    o.x = (y.x - mu)*ri*w.x + gb.x;
    o.y = (y.y - mu)*ri*w.y + gb.y;
    o.z = (y.z - mu)*ri*w.z + gb.z;
    o.w = (y.w - mu)*ri*w.w + gb.w;
    *(float4*)(g_Yn + (size_t)m*CC + k) = o;
}

// ---------------------------------------------------------------------------
extern "C" void kernel_launch(void* const* d_in, const int* in_sizes, int n_in,
                              void* d_out, int out_size) {
    const float* x   = (const float*)d_in[0];
    const float* Wq  = (const float*)d_in[1];
    const float* Wk  = (const float*)d_in[2];
    const float* Wv  = (const float*)d_in[3];
    const float* Wo  = (const float*)d_in[4];
    const float* gnw = (const float*)d_in[5];
    const float* gnb = (const float*)d_in[6];
    float* out = (float*)d_out;

    cudaFuncSetAttribute(gemm_kernel,
                         cudaFuncAttributeMaxDynamicSharedMemorySize, GEMM_SMEM);
    cudaFuncSetAttribute(retention_kernel,
                         cudaFuncAttributeMaxDynamicSharedMemorySize, RET_SMEM);

    dim3 gg(MM/128, CC/128);  // 32 x 8

    gemm_kernel<<<gg, 256, GEMM_SMEM>>>(x, Wq, nullptr, 0, 0.125f);
    gemm_kernel<<<gg, 256, GEMM_SMEM>>>(x, Wk, nullptr, 1, 1.0f);
    gemm_kernel<<<gg, 256, GEMM_SMEM>>>(x, Wv, nullptr, 2, 1.0f);

    vt_kernel<<<dim3(TT/64, BB*HH), 256>>>();

    retention_kernel<<<dim3(QT2, BB*HH), 256, RET_SMEM>>>();

    norm_stats_kernel<<<1, 32>>>();
    yn_kernel<<<MM, 256>>>(gnw, gnb);

    gemm_kernel<<<gg, 256, GEMM_SMEM>>>(nullptr, Wo, out, 3, 1.0f);
}

// round 17
// speedup vs baseline: 1.1417x; 1.1417x over previous
#include <cuda_runtime.h>
#include <cuda_bf16.h>
#include <math.h>
#include <stdint.h>

#define BB 2
#define TT 2048
#define CC 1024
#define HH 16
#define DD 64
#define MM (BB*TT)      // 4096
#define QT2 16          // 128-row query tiles

// Scratch (device globals: allocation-free, graph-capture safe)
__device__ float g_V[BB*HH*TT*DD];
__device__ float g_Y[BB*HH*TT*DD];
__device__ __nv_bfloat16 g_Ah[MM*CC], g_Al[MM*CC];        // GEMM A operand
__device__ __nv_bfloat16 g_Wh[3*CC*CC], g_Wl[3*CC*CC];    // 3 weight slots
__device__ __nv_bfloat16 g_Qh[BB*HH*TT*DD], g_Ql[BB*HH*TT*DD];
__device__ __nv_bfloat16 g_Kh[BB*HH*TT*DD], g_Kl[BB*HH*TT*DD];
__device__ __nv_bfloat16 g_Vth[BB*HH*DD*TT], g_Vtl[BB*HH*DD*TT];  // [bh][d][t]
__device__ float g_part[BB*HH*QT2*2];
__device__ float g_norm[BB*HH*2];

// ===========================================================================
// mma.sync bf16 (baseline ISA — sm_103-safe; validated R8-R15)
// ===========================================================================
__device__ __forceinline__ void mma16816(float d[4], const uint32_t a[4],
                                         const uint32_t b[2]) {
    asm volatile(
        "mma.sync.aligned.m16n8k16.row.col.f32.bf16.bf16.f32 "
        "{%0,%1,%2,%3}, {%4,%5,%6,%7}, {%8,%9}, {%0,%1,%2,%3};"
        : "+f"(d[0]), "+f"(d[1]), "+f"(d[2]), "+f"(d[3])
        : "r"(a[0]), "r"(a[1]), "r"(a[2]), "r"(a[3]), "r"(b[0]), "r"(b[1]));
}

__device__ __forceinline__ void cvt_pair(float a, float b, uint32_t& hi, uint32_t& lo) {
    __nv_bfloat162 h, l;
    h.x = __float2bfloat16(a); h.y = __float2bfloat16(b);
    l.x = __float2bfloat16(a - __bfloat162float(h.x));
    l.y = __float2bfloat16(b - __bfloat162float(h.y));
    hi = *(uint32_t*)&h; lo = *(uint32_t*)&l;
}

// ===========================================================================
// Elementwise fp32 -> (bf16 hi, bf16 lo) split. Destinations resolved ON
// DEVICE. which: 0 -> g_Ah/g_Al;  1/2/3 -> g_Wh/g_Wl slot (which-1).
// ===========================================================================
__global__ void split_kernel(const float* __restrict__ src, int which, int n4) {
    int i = blockIdx.x * blockDim.x + threadIdx.x;
    if (i < n4) {
        __nv_bfloat16* dh;
        __nv_bfloat16* dl;
        if (which == 0) { dh = g_Ah; dl = g_Al; }
        else { dh = g_Wh + (size_t)(which-1)*CC*CC; dl = g_Wl + (size_t)(which-1)*CC*CC; }
        float4 v = ((const float4*)src)[i];
        uint32_t h0, l0, h1, l1;
        cvt_pair(v.x, v.y, h0, l0); cvt_pair(v.z, v.w, h1, l1);
        ((uint2*)dh)[i] = make_uint2(h0, h1);
        ((uint2*)dl)[i] = make_uint2(l0, l1);
    }
}

// ===========================================================================
// Split-bf16 GEMM: D[m,n] = sum_k A[m,k] * W[n,k]; operands PRE-SPLIT.
// CTA 128x128, Kch 64, 256 thr, warps 4x2, warp tile 32x64, loader = raw
// bf16 uint4 copies. mode_arg = -1: FUSED QKV (mode = blockIdx.z, weight
// slot z); mode_arg = 3: output GEMM (weight slot 0, A = g_Ah from yn).
// mode 0: Q -> g_Qh/g_Ql (scaled 0.125); 1: K; 2: V f32; 3: OutDirect.
// ===========================================================================
#define KCH 64
#define STR 72
#define TILE_U (128*STR)
#define GEMM_SMEM (4*TILE_U*2)           // 73728 B  (2 CTAs/SM fits)

__global__ void __launch_bounds__(256, 2)
gemm_kernel(float* __restrict__ OutDirect, int mode_arg) {
    extern __shared__ __nv_bfloat16 smB[];
    __nv_bfloat16* Ahi = smB;
    __nv_bfloat16* Alo = smB + TILE_U;
    __nv_bfloat16* Bhi = smB + 2*TILE_U;
    __nv_bfloat16* Blo = smB + 3*TILE_U;

    int mode = (mode_arg < 0) ? (int)blockIdx.z : mode_arg;
    int wslot = (mode_arg < 0) ? (int)blockIdx.z : 0;
    float scale = (mode == 0) ? 0.125f : 1.0f;

    int tid = threadIdx.x;
    int wid = tid >> 5, lane = tid & 31;
    int g = lane >> 2, tg = lane & 3;
    int wm = wid >> 1, wn = wid & 1;
    int m0 = blockIdx.x * 128, n0 = blockIdx.y * 128;

    int lrow = tid >> 1, lhalf = (tid & 1) * 32;
    const __nv_bfloat16* Ah = g_Ah + (size_t)(m0 + lrow) * CC + lhalf;
    const __nv_bfloat16* Al = g_Al + (size_t)(m0 + lrow) * CC + lhalf;
    const __nv_bfloat16* Bh = g_Wh + (size_t)wslot*CC*CC + (size_t)(n0 + lrow) * CC + lhalf;
    const __nv_bfloat16* Bl = g_Wl + (size_t)wslot*CC*CC + (size_t)(n0 + lrow) * CC + lhalf;

    float acc[2][8][4] = {};

    for (int k0 = 0; k0 < CC; k0 += KCH) {
        int u = lrow*STR + lhalf;
        #pragma unroll
        for (int j = 0; j < 4; j++) {
            *(uint4*)(Ahi + u + j*8) = *(const uint4*)(Ah + k0 + j*8);
            *(uint4*)(Alo + u + j*8) = *(const uint4*)(Al + k0 + j*8);
            *(uint4*)(Bhi + u + j*8) = *(const uint4*)(Bh + k0 + j*8);
            *(uint4*)(Blo + u + j*8) = *(const uint4*)(Bl + k0 + j*8);
        }
        __syncthreads();

        #pragma unroll
        for (int ks = 0; ks < 4; ks++) {
            int kc = ks*16 + tg*2;
            uint32_t ah[2][4], al[2][4];
            #pragma unroll
            for (int mf = 0; mf < 2; mf++) {
                int r = wm*32 + mf*16 + g;
                ah[mf][0] = *(const uint32_t*)(Ahi + (r  )*STR + kc);
                ah[mf][1] = *(const uint32_t*)(Ahi + (r+8)*STR + kc);
                ah[mf][2] = *(const uint32_t*)(Ahi + (r  )*STR + kc + 8);
                ah[mf][3] = *(const uint32_t*)(Ahi + (r+8)*STR + kc + 8);
                al[mf][0] = *(const uint32_t*)(Alo + (r  )*STR + kc);
                al[mf][1] = *(const uint32_t*)(Alo + (r+8)*STR + kc);
                al[mf][2] = *(const uint32_t*)(Alo + (r  )*STR + kc + 8);
                al[mf][3] = *(const uint32_t*)(Alo + (r+8)*STR + kc + 8);
            }
            #pragma unroll
            for (int nf = 0; nf < 8; nf++) {
                int n = wn*64 + nf*8 + g;
                uint32_t bh[2], bl[2];
                bh[0] = *(const uint32_t*)(Bhi + n*STR + kc);
                bh[1] = *(const uint32_t*)(Bhi + n*STR + kc + 8);
                bl[0] = *(const uint32_t*)(Blo + n*STR + kc);
                bl[1] = *(const uint32_t*)(Blo + n*STR + kc + 8);
                #pragma unroll
                for (int mf = 0; mf < 2; mf++) {
                    mma16816(acc[mf][nf], ah[mf], bh);
                    mma16816(acc[mf][nf], ah[mf], bl);
                    mma16816(acc[mf][nf], al[mf], bh);
                }
            }
        }
        __syncthreads();
    }

    if (mode == 3) {
        #pragma unroll
        for (int mf = 0; mf < 2; mf++) {
            int m = m0 + wm*32 + mf*16 + g;
            #pragma unroll
            for (int nf = 0; nf < 8; nf++) {
                int n = n0 + wn*64 + nf*8 + tg*2;
                float* d = acc[mf][nf];
                *(float2*)(OutDirect + (size_t)m*CC + n)     = make_float2(d[0], d[1]);
                *(float2*)(OutDirect + (size_t)(m+8)*CC + n) = make_float2(d[2], d[3]);
            }
        }
    } else if (mode == 2) {
        #pragma unroll
        for (int mf = 0; mf < 2; mf++) {
            int m = m0 + wm*32 + mf*16 + g;
            int b = m >> 11, t = m & (TT - 1);
            #pragma unroll
            for (int nf = 0; nf < 8; nf++) {
                int n = n0 + wn*64 + nf*8 + tg*2;
                int h = n >> 6, d0 = n & 63;
                float* d = acc[mf][nf];
                size_t base = ((size_t)(b*HH + h)*TT);
                *(float2*)(g_V + (base + t  )*DD + d0) = make_float2(d[0], d[1]);
                *(float2*)(g_V + (base + t+8)*DD + d0) = make_float2(d[2], d[3]);
            }
        }
    } else {
        __nv_bfloat16* Oh = (mode == 0) ? g_Qh : g_Kh;
        __nv_bfloat16* Ol = (mode == 0) ? g_Ql : g_Kl;
        #pragma unroll
        for (int mf = 0; mf < 2; mf++) {
            int m = m0 + wm*32 + mf*16 + g;
            int b = m >> 11, t = m & (TT - 1);
            #pragma unroll
            for (int nf = 0; nf < 8; nf++) {
                int n = n0 + wn*64 + nf*8 + tg*2;
                int h = n >> 6, d0 = n & 63;
                float* d = acc[mf][nf];
                size_t base = ((size_t)(b*HH + h)*TT);
                uint32_t h0, l0, h1, l1;
                cvt_pair(d[0]*scale, d[1]*scale, h0, l0);
                cvt_pair(d[2]*scale, d[3]*scale, h1, l1);
                *(uint32_t*)(Oh + (base + t  )*DD + d0) = h0;
                *(uint32_t*)(Ol + (base + t  )*DD + d0) = l0;
                *(uint32_t*)(Oh + (base + t+8)*DD + d0) = h1;
                *(uint32_t*)(Ol + (base + t+8)*DD + d0) = l1;
            }
        }
    }
}

// ===========================================================================
// V transpose + split: g_V [bh][t][d] f32 -> g_Vth/g_Vtl [bh][d][t] bf16
// ===========================================================================
__global__ void vt_kernel() {
    __shared__ float ts[64][65];
    int bh = blockIdx.y, t0 = blockIdx.x * 64;
    size_t base = (size_t)bh * TT * DD;
    int tid = threadIdx.x;
    int r = tid >> 2, c = (tid & 3) * 16;

    #pragma unroll
    for (int i = 0; i < 4; i++) {
        float4 v = *(const float4*)(g_V + base + (size_t)(t0 + r)*DD + c + i*4);
        ts[r][c + i*4 + 0] = v.x; ts[r][c + i*4 + 1] = v.y;
        ts[r][c + i*4 + 2] = v.z; ts[r][c + i*4 + 3] = v.w;
    }
    __syncthreads();

    uint32_t hh[8], ll[8];
    #pragma unroll
    for (int p = 0; p < 8; p++)
        cvt_pair(ts[c + 2*p][r], ts[c + 2*p + 1][r], hh[p], ll[p]);
    size_t o = base + (size_t)r*TT + t0 + c;
    *(uint4*)(g_Vth + o)     = make_uint4(hh[0], hh[1], hh[2], hh[3]);
    *(uint4*)(g_Vth + o + 8) = make_uint4(hh[4], hh[5], hh[6], hh[7]);
    *(uint4*)(g_Vtl + o)     = make_uint4(ll[0], ll[1], ll[2], ll[3]);
    *(uint4*)(g_Vtl + o + 8) = make_uint4(ll[4], ll[5], ll[6], ll[7]);
}

// ===========================================================================
// Retention, bf16 split tensor-core version (unchanged from R15 passing).
// ===========================================================================
#define RSTR 72
#define RET_SMEM ((128*RSTR*2 + 64*RSTR*4) * 2)   // 73728 B

__global__ void __launch_bounds__(256, 2) retention_kernel() {
    extern __shared__ __nv_bfloat16 sb[];
    __nv_bfloat16* SQh = sb;
    __nv_bfloat16* SQl = sb + 128*RSTR;
    __nv_bfloat16* SKh = sb + 256*RSTR;
    __nv_bfloat16* SKl = sb + 320*RSTR;
    __nv_bfloat16* SVh = sb + 384*RSTR;
    __nv_bfloat16* SVl = sb + 448*RSTR;
    __shared__ float red[16];

    int tid = threadIdx.x;
    int w = tid >> 5, lane = tid & 31, g = lane >> 2, tg = lane & 3;
    int qt = (QT2 - 1) - blockIdx.x;           // heavy tiles first
    int bh = blockIdx.y;
    int h = bh & (HH - 1);
    int i0 = qt * 128;
    size_t base = (size_t)bh * TT * DD;

    float lg = log2f(1.0f - exp2f(-5.0f - 0.5f * (float)h));

    // load Q tile (128 x 64) hi/lo
    {
        int r = tid >> 1, sq = (tid & 1) * 32;
        const __nv_bfloat16* qh = g_Qh + base + (size_t)(i0 + r)*DD + sq;
        const __nv_bfloat16* ql = g_Ql + base + (size_t)(i0 + r)*DD + sq;
        #pragma unroll
        for (int cch = 0; cch < 4; cch++) {
            *(uint4*)(SQh + r*RSTR + sq + cch*8) = *(const uint4*)(qh + cch*8);
            *(uint4*)(SQl + r*RSTR + sq + cch*8) = *(const uint4*)(ql + cch*8);
        }
    }

    // constant decay factors (reg-lean)
    float rowA = exp2f(lg * (float)(w*16 + g));
    float rowB = rowA * exp2f(lg * 8.0f);
    float cstep = exp2f(-lg);
    float cf0[8];
    #pragma unroll
    for (int nf = 0; nf < 8; nf++)
        cf0[nf] = exp2f(-lg * (float)(nf*8 + tg*2));

    float acc_o[8][4] = {};
    int r4 = tid >> 2, s4 = (tid & 3) * 16;
    int jend = i0 + 128;

    for (int j0 = 0; j0 < jend; j0 += 64) {
        __syncthreads();
        {
            const __nv_bfloat16* kh = g_Kh + base + (size_t)(j0 + r4)*DD + s4;
            const __nv_bfloat16* kl = g_Kl + base + (size_t)(j0 + r4)*DD + s4;
            const __nv_bfloat16* vh = g_Vth + base + (size_t)r4*TT + j0 + s4;
            const __nv_bfloat16* vl = g_Vtl + base + (size_t)r4*TT + j0 + s4;
            *(uint4*)(SKh + r4*RSTR + s4)     = *(const uint4*)(kh);
            *(uint4*)(SKh + r4*RSTR + s4 + 8) = *(const uint4*)(kh + 8);
            *(uint4*)(SKl + r4*RSTR + s4)     = *(const uint4*)(kl);
            *(uint4*)(SKl + r4*RSTR + s4 + 8) = *(const uint4*)(kl + 8);
            *(uint4*)(SVh + r4*RSTR + s4)     = *(const uint4*)(vh);
            *(uint4*)(SVh + r4*RSTR + s4 + 8) = *(const uint4*)(vh + 8);
            *(uint4*)(SVl + r4*RSTR + s4)     = *(const uint4*)(vl);
            *(uint4*)(SVl + r4*RSTR + s4 + 8) = *(const uint4*)(vl + 8);
        }
        __syncthreads();

        int iMin = i0 + w*16, iMax = iMin + 15, jMax = j0 + 63;
        if (iMax < j0) continue;

        // ---- S = Q K^T ----
        float s[8][4] = {};
        #pragma unroll
        for (int ks = 0; ks < 4; ks++) {
            int kc = ks*16 + tg*2;
            int ra = (w*16 + g)*RSTR, rb = ra + 8*RSTR;
            uint32_t ah[4], al[4];
            ah[0] = *(const uint32_t*)(SQh + ra + kc);
            ah[1] = *(const uint32_t*)(SQh + rb + kc);
            ah[2] = *(const uint32_t*)(SQh + ra + kc + 8);
            ah[3] = *(const uint32_t*)(SQh + rb + kc + 8);
            al[0] = *(const uint32_t*)(SQl + ra + kc);
            al[1] = *(const uint32_t*)(SQl + rb + kc);
            al[2] = *(const uint32_t*)(SQl + ra + kc + 8);
            al[3] = *(const uint32_t*)(SQl + rb + kc + 8);
            #pragma unroll
            for (int nf = 0; nf < 8; nf++) {
                int n = (nf*8 + g)*RSTR;
                uint32_t bh2[2], bl2[2];
                bh2[0] = *(const uint32_t*)(SKh + n + kc);
                bh2[1] = *(const uint32_t*)(SKh + n + kc + 8);
                bl2[0] = *(const uint32_t*)(SKl + n + kc);
                bl2[1] = *(const uint32_t*)(SKl + n + kc + 8);
                mma16816(s[nf], ah, bh2);
                mma16816(s[nf], ah, bl2);
                mma16816(s[nf], al, bh2);
            }
        }

        // ---- decay / causal mask ----
        if (iMin >= jMax) {
            float tf = exp2f(lg * (float)(i0 - j0));
            float fA = rowA * tf, fB = rowB * tf;
            #pragma unroll
            for (int nf = 0; nf < 8; nf++) {
                float c0 = cf0[nf], c1 = c0 * cstep;
                s[nf][0] *= fA * c0;
                s[nf][1] *= fA * c1;
                s[nf][2] *= fB * c0;
                s[nf][3] *= fB * c1;
            }
        } else {
            int riA = iMin + g, riB = riA + 8;
            #pragma unroll
            for (int nf = 0; nf < 8; nf++) {
                int jg = j0 + nf*8 + tg*2;
                int d0 = riA - jg, d1 = d0 - 1, d2 = riB - jg, d3 = d2 - 1;
                s[nf][0] = (d0 >= 0) ? s[nf][0] * exp2f(lg * (float)d0) : 0.0f;
                s[nf][1] = (d1 >= 0) ? s[nf][1] * exp2f(lg * (float)d1) : 0.0f;
                s[nf][2] = (d2 >= 0) ? s[nf][2] * exp2f(lg * (float)d2) : 0.0f;
                s[nf][3] = (d3 >= 0) ? s[nf][3] * exp2f(lg * (float)d3) : 0.0f;
            }
        }

        // ---- O += S V ----
        #pragma unroll
        for (int ks = 0; ks < 4; ks++) {
            uint32_t sh[4], sl[4];
            cvt_pair(s[2*ks  ][0], s[2*ks  ][1], sh[0], sl[0]);
            cvt_pair(s[2*ks  ][2], s[2*ks  ][3], sh[1], sl[1]);
            cvt_pair(s[2*ks+1][0], s[2*ks+1][1], sh[2], sl[2]);
            cvt_pair(s[2*ks+1][2], s[2*ks+1][3], sh[3], sl[3]);
            int kc = ks*16 + tg*2;
            #pragma unroll
            for (int nd = 0; nd < 8; nd++) {
                int n = (nd*8 + g)*RSTR;
                uint32_t vh[2], vl[2];
                vh[0] = *(const uint32_t*)(SVh + n + kc);
                vh[1] = *(const uint32_t*)(SVh + n + kc + 8);
                vl[0] = *(const uint32_t*)(SVl + n + kc);
                vl[1] = *(const uint32_t*)(SVl + n + kc + 8);
                mma16816(acc_o[nd], sh, vh);
                mma16816(acc_o[nd], sh, vl);
                mma16816(acc_o[nd], sl, vh);
            }
        }
    }

    // ---- write y + GroupNorm partial stats ----
    float lsum = 0.0f, lsq = 0.0f;
    int riA = i0 + w*16 + g;
    #pragma unroll
    for (int nd = 0; nd < 8; nd++) {
        int d0 = nd*8 + tg*2;
        float* d = acc_o[nd];
        lsum += d[0] + d[1] + d[2] + d[3];
        lsq  += d[0]*d[0] + d[1]*d[1] + d[2]*d[2] + d[3]*d[3];
        *(float2*)(g_Y + base + (size_t)riA*DD + d0)     = make_float2(d[0], d[1]);
        *(float2*)(g_Y + base + (size_t)(riA+8)*DD + d0) = make_float2(d[2], d[3]);
    }
    #pragma unroll
    for (int o = 16; o > 0; o >>= 1) {
        lsum += __shfl_down_sync(0xffffffffu, lsum, o);
        lsq  += __shfl_down_sync(0xffffffffu, lsq,  o);
    }
    if (lane == 0) { red[w*2] = lsum; red[w*2 + 1] = lsq; }
    __syncthreads();
    if (tid == 0) {
        float s0 = 0.0f, s1 = 0.0f;
        #pragma unroll
        for (int x = 0; x < 8; x++) { s0 += red[x*2]; s1 += red[x*2 + 1]; }
        g_part[(bh*QT2 + qt)*2 + 0] = s0;
        g_part[(bh*QT2 + qt)*2 + 1] = s1;
    }
}

__global__ void norm_stats_kernel() {
    int i = threadIdx.x;
    if (i < BB*HH) {
        float s = 0.0f, q = 0.0f;
        for (int t = 0; t < QT2; t++) {
            s += g_part[(i*QT2 + t)*2 + 0];
            q += g_part[(i*QT2 + t)*2 + 1];
        }
        float n = (float)(TT * DD);
        float mu = s / n;
        float var = q / n - mu * mu;
        g_norm[i*2 + 0] = mu;
        g_norm[i*2 + 1] = rsqrtf(var + 1e-5f);
    }
}

// GroupNorm apply -> g_Ah/g_Al (pre-split bf16 A operand for the output GEMM)
__global__ void yn_kernel(const float* __restrict__ gnw, const float* __restrict__ gnb) {
    int m = blockIdx.x;
    int k = threadIdx.x * 4;
    int b = m >> 11, t = m & (TT - 1);
    int h = k >> 6, d = k & 63;
    int bh = b*HH + h;
    float mu = g_norm[bh*2 + 0], ri = g_norm[bh*2 + 1];
    float4 y = *(const float4*)(g_Y + ((size_t)bh*TT + t)*DD + d);
    float4 w = *(const float4*)(gnw + k);
    float4 gb = *(const float4*)(gnb + k);
    float o0 = (y.x - mu)*ri*w.x + gb.x;
    float o1 = (y.y - mu)*ri*w.y + gb.y;
    float o2 = (y.z - mu)*ri*w.z + gb.z;
    float o3 = (y.w - mu)*ri*w.w + gb.w;
    uint32_t h0, l0, h1, l1;
    cvt_pair(o0, o1, h0, l0); cvt_pair(o2, o3, h1, l1);
    size_t o = (size_t)m*CC + k;
    *(uint2*)(g_Ah + o) = make_uint2(h0, h1);
    *(uint2*)(g_Al + o) = make_uint2(l0, l1);
}

// ---------------------------------------------------------------------------
extern "C" void kernel_launch(void* const* d_in, const int* in_sizes, int n_in,
                              void* d_out, int out_size) {
    const float* x   = (const float*)d_in[0];
    const float* Wq  = (const float*)d_in[1];
    const float* Wk  = (const float*)d_in[2];
    const float* Wv  = (const float*)d_in[3];
    const float* Wo  = (const float*)d_in[4];
    const float* gnw = (const float*)d_in[5];
    const float* gnb = (const float*)d_in[6];
    float* out = (float*)d_out;

    cudaFuncSetAttribute(gemm_kernel,
                         cudaFuncAttributeMaxDynamicSharedMemorySize, GEMM_SMEM);
    cudaFuncSetAttribute(retention_kernel,
                         cudaFuncAttributeMaxDynamicSharedMemorySize, RET_SMEM);

    const int XN4 = MM*CC/4, WN4 = CC*CC/4;

    split_kernel<<<(XN4 + 255)/256, 256>>>(x, 0, XN4);
    split_kernel<<<(WN4 + 255)/256, 256>>>(Wq, 1, WN4);
    split_kernel<<<(WN4 + 255)/256, 256>>>(Wk, 2, WN4);
    split_kernel<<<(WN4 + 255)/256, 256>>>(Wv, 3, WN4);

    // Fused QKV: one launch, grid.z selects weight slot + epilogue
    gemm_kernel<<<dim3(MM/128, CC/128, 3), 256, GEMM_SMEM>>>(nullptr, -1);

    vt_kernel<<<dim3(TT/64, BB*HH), 256>>>();

    retention_kernel<<<dim3(QT2, BB*HH), 256, RET_SMEM>>>();

    norm_stats_kernel<<<1, 32>>>();
    yn_kernel<<<MM, 256>>>(gnw, gnb);

    split_kernel<<<(WN4 + 255)/256, 256>>>(Wo, 1, WN4);
    gemm_kernel<<<dim3(MM/128, CC/128, 1), 256, GEMM_SMEM>>>(out, 3);
}